// round 10
// baseline (speedup 1.0000x reference)
#include <cuda_runtime.h>
#include <cuda_fp16.h>
#include <math.h>

// features [N=2, C=256, H=200, W=200] f32  (NCHW input)
// rois     [R=512, 5] f32
// masks    [R=512, 128, 128] f32
// out      [R, 256, 7, 7] f32
#define NIMG  2
#define C_CH  256
#define FH    200
#define FW    200
#define PIX   (FH * FW)
#define MH    128
#define MW    128
#define NSAMP 196
#define SCALE 0.25f
#define SOUT_LD 264   // 256 channels + 8 pad

// NHWC fp16 feature copy: 2*40000*256 halves = 40.96 MB
__device__ __align__(16) __half g_fth[(size_t)NIMG * PIX * C_CH];

// ---------------- NCHW f32 -> NHWC f16 transpose ----------------
__global__ __launch_bounds__(256)
void transpose_kernel(const float* __restrict__ feat)
{
    __shared__ float tile[32][65];        // [pixel][channel]
    const int p0  = blockIdx.x * 32;
    const int c0  = blockIdx.y * 64;
    const int img = blockIdx.z;
    const int tx = threadIdx.x;           // 0..31
    const int ty = threadIdx.y;           // 0..7

    const float* in = feat + (size_t)img * C_CH * PIX;
#pragma unroll
    for (int k = 0; k < 8; ++k) {
        const int c = ty + k * 8;         // 0..63
        tile[tx][c] = in[(size_t)(c0 + c) * PIX + p0 + tx];
    }
    __syncthreads();

    __half* outp = g_fth + (size_t)img * PIX * C_CH;
#pragma unroll
    for (int k = 0; k < 4; ++k) {
        const int p = ty + k * 8;         // 0..31
        const float v0 = tile[p][2 * tx];
        const float v1 = tile[p][2 * tx + 1];
        const __half2 h = __floats2half2_rn(v0, v1);
        *(__half2*)(outp + (size_t)(p0 + p) * C_CH + c0 + 2 * tx) = h;
    }
}

// ---------------- mask-weighted RoIAlign on NHWC f16 features ----------------
__device__ __forceinline__ __half2 u2h2(unsigned u)
{
    return *reinterpret_cast<__half2*>(&u);
}

__global__ __launch_bounds__(256, 6)
void roialign_kernel(const float* __restrict__ rois,
                     const float* __restrict__ masks,
                     float* __restrict__ out)
{
    __shared__ int     s_o00[NSAMP], s_o01[NSAMP], s_o10[NSAMP], s_o11[NSAMP];
    __shared__ __half2 s_h00[NSAMP], s_h01[NSAMP], s_h10[NSAMP], s_h11[NSAMP];
    __shared__ float   s_out[25 * SOUT_LD];     // <= 25 bins per block

    const int r = blockIdx.x;
    const int t = threadIdx.x;

    const float* roi = rois + (size_t)r * 5;
    const int   b   = (int)roi[0];
    const float rx1 = roi[1], ry1 = roi[2], rx2 = roi[3], ry2 = roi[4];

    const float rsw = rx1 * SCALE;
    const float rsh = ry1 * SCALE;
    const float rw  = fmaxf((rx2 - rx1 + 1.0f) * SCALE, 1.0f);
    const float rh  = fmaxf((ry2 - ry1 + 1.0f) * SCALE, 1.0f);
    const float bw  = rw * (1.0f / 7.0f);
    const float bh  = rh * (1.0f / 7.0f);

    // ---- phase 1: per-sample corner offsets + half2-packed combined weights ----
    if (t < NSAMP) {
        const int iy = t / 14;
        const int ix = t - iy * 14;
        const float y = rsh + ((float)iy * 0.5f + 0.25f) * bh;
        const float x = rsw + ((float)ix * 0.5f + 0.25f) * bw;

        const bool valid = (y > -1.0f) && (y < (float)FH) &&
                           (x > -1.0f) && (x < (float)FW);

        const float yc = fminf(fmaxf(y, 0.0f), (float)(FH - 1));
        const float xc = fminf(fmaxf(x, 0.0f), (float)(FW - 1));
        const int y0  = (int)floorf(yc);
        const int x0  = (int)floorf(xc);
        const int y1i = min(y0 + 1, FH - 1);
        const int x1i = min(x0 + 1, FW - 1);
        const float ly = yc - (float)y0;
        const float lx = xc - (float)x0;
        const float hy = 1.0f - ly;
        const float hx = 1.0f - lx;

        const float my = fminf(fmaxf(y * 4.0f - ry1, 0.0f), ry2 - ry1);
        const float mx = fminf(fmaxf(x * 4.0f - rx1, 0.0f), rx2 - rx1);
        const int  my0 = (int)floorf(my);
        const int  mx0 = (int)floorf(mx);
        const int  my1 = min(my0 + 1, MH - 1);
        const int  mx1 = min(mx0 + 1, MW - 1);
        const float lmy = my - (float)my0;
        const float lmx = mx - (float)mx0;
        const float hmy = 1.0f - lmy;
        const float hmx = 1.0f - lmx;

        const float* mp = masks + (size_t)r * (MH * MW);
        const float wgt = hmy * hmx * __ldg(mp + my0 * MW + mx0)
                        + hmy * lmx * __ldg(mp + my0 * MW + mx1)
                        + lmy * hmx * __ldg(mp + my1 * MW + mx0)
                        + lmy * lmx * __ldg(mp + my1 * MW + mx1);

        const float wv = valid ? wgt : 0.0f;

        const int base = b * PIX;
        s_o00[t] = (base + y0  * FW + x0 ) * C_CH;
        s_o01[t] = (base + y0  * FW + x1i) * C_CH;
        s_o10[t] = (base + y1i * FW + x0 ) * C_CH;
        s_o11[t] = (base + y1i * FW + x1i) * C_CH;
        s_h00[t] = __float2half2_rn(wv * hy * hx);
        s_h01[t] = __float2half2_rn(wv * hy * lx);
        s_h10[t] = __float2half2_rn(wv * ly * hx);
        s_h11[t] = __float2half2_rn(wv * ly * lx);
    }
    __syncthreads();

    // ---- phase 2: lane = 8 channels, HFMA2 blend per sample, f32 cross-sample acc ----
    const int warp = t >> 5;
    const int lane = t & 31;
    const int c8   = lane * 8;
    const __half* __restrict__ ftc = g_fth + c8;

    const int b0 = blockIdx.y * 25;                // bins [b0, b0+nb)
    const int nb = blockIdx.y ? 24 : 25;

    for (int ib = warp; ib < nb; ib += 8) {
        const int bin = b0 + ib;
        const int by = bin / 7;
        const int bx = bin - by * 7;
        const int s0 = by * 28 + bx * 2;

        float2 accf[4];
#pragma unroll
        for (int q = 0; q < 4; ++q) accf[q] = make_float2(0.f, 0.f);

#pragma unroll
        for (int j = 0; j < 4; ++j) {
            const int si = s0 + ((j >> 1) * 14) + (j & 1);
            const __half2 w0 = s_h00[si];
            const __half2 w1 = s_h01[si];
            const __half2 w2 = s_h10[si];
            const __half2 w3 = s_h11[si];
            const uint4 u0 = __ldg((const uint4*)(ftc + s_o00[si]));
            const uint4 u1 = __ldg((const uint4*)(ftc + s_o01[si]));
            const uint4 u2 = __ldg((const uint4*)(ftc + s_o10[si]));
            const uint4 u3 = __ldg((const uint4*)(ftc + s_o11[si]));

            const unsigned a0[4] = {u0.x, u0.y, u0.z, u0.w};
            const unsigned a1[4] = {u1.x, u1.y, u1.z, u1.w};
            const unsigned a2[4] = {u2.x, u2.y, u2.z, u2.w};
            const unsigned a3[4] = {u3.x, u3.y, u3.z, u3.w};
#pragma unroll
            for (int q = 0; q < 4; ++q) {
                __half2 s = __hmul2(u2h2(a0[q]), w0);
                s = __hfma2(u2h2(a1[q]), w1, s);
                s = __hfma2(u2h2(a2[q]), w2, s);
                s = __hfma2(u2h2(a3[q]), w3, s);
                const float2 f = __half22float2(s);
                accf[q].x += f.x;
                accf[q].y += f.y;
            }
        }

        float* sp = &s_out[ib * SOUT_LD + c8];
        *(float4*)(sp)     = make_float4(accf[0].x * 0.25f, accf[0].y * 0.25f,
                                         accf[1].x * 0.25f, accf[1].y * 0.25f);
        *(float4*)(sp + 4) = make_float4(accf[2].x * 0.25f, accf[2].y * 0.25f,
                                         accf[3].x * 0.25f, accf[3].y * 0.25f);
    }
    __syncthreads();

    // ---- flush: coalesced stores out[r][cc][b0..b0+nb) ----
    float* op = out + (size_t)r * C_CH * 49 + b0;
    for (int cc = warp; cc < C_CH; cc += 8)
        for (int k = lane; k < nb; k += 32)
            op[cc * 49 + k] = s_out[k * SOUT_LD + cc];
}

extern "C" void kernel_launch(void* const* d_in, const int* in_sizes, int n_in,
                              void* d_out, int out_size)
{
    const float* feat  = (const float*)d_in[0];
    const float* rois  = (const float*)d_in[1];
    const float* masks = (const float*)d_in[2];
    float* out = (float*)d_out;

    const int R = in_sizes[1] / 5;   // 512

    dim3 tgrid(PIX / 32, C_CH / 64, NIMG);   // 1250 x 4 x 2
    dim3 tblk(32, 8);
    transpose_kernel<<<tgrid, tblk>>>(feat);

    dim3 rgrid(R, 2);
    roialign_kernel<<<rgrid, 256>>>(rois, masks, out);
}